// round 6
// baseline (speedup 1.0000x reference)
#include <cuda_runtime.h>

#define HW   4096
#define C    128
#define CR   32
#define G    8
#define CG   16
#define KK   49
#define KKG  392
#define NPX  16384   // B * H * W

typedef unsigned long long u64;

// ---- packed f32x2 helpers (sm_103a) ---------------------------------------
__device__ __forceinline__ u64 pack2(float x, float y) {
    u64 r; asm("mov.b64 %0, {%1, %2};" : "=l"(r) : "f"(x), "f"(y)); return r;
}
__device__ __forceinline__ void unpack2(u64 v, float& x, float& y) {
    asm("mov.b64 {%0, %1}, %2;" : "=f"(x), "=f"(y) : "l"(v));
}
__device__ __forceinline__ void ffma2(u64& d, u64 a, u64 b) {
    asm("fma.rn.f32x2 %0, %1, %2, %0;" : "+l"(d) : "l"(a), "l"(b));
}

// Scratch (16B-aligned: we do float2/u64 accesses into these)
__device__ __align__(16) float g_red[NPX * CR];        // [px][32]
__device__ __align__(16) float g_ker[4 * KKG * HW];    // [b][392][hw]

// ---------------------------------------------------------------------------
// Kernel 1: red[px][o] = sum_c x[b,c,hw] * w_reduce[o,c] + b_reduce[o]
// lane = out (32 outs = warp), warp owns 4 px. Tile 32 px -> grid 512.
// Double-buffered x chunks (prefetch regs during compute, 1 sync/iter).
// ---------------------------------------------------------------------------
__global__ __launch_bounds__(256) void k_reduce(const float* __restrict__ x,
                                                const float* __restrict__ wr,
                                                const float* __restrict__ br) {
    __shared__ float wsT[C][CR + 2];    // [c][o], even pad -> 8B rows
    __shared__ float xs[2][32][32];     // ping-pong [k][px]
    const int tid  = threadIdx.x;
    const int lane = tid & 31;          // = out channel
    const int warp = tid >> 5;
    const int pxw  = warp * 4;          // warp's px base (4 px/warp)
    const int px0  = blockIdx.x * 32;
    const int b    = px0 >> 12;
    const int hw0  = px0 & 4095;
    const float* xb = x + (size_t)b * C * HW + hw0;

    const int prow = tid >> 5;          // reuse warp as row-part? no: idx math below
    (void)prow;

    // stage w_reduce transposed once: wsT[c][o]
#pragma unroll
    for (int l = 0; l < 16; l++) {
        int idx = tid + l * 256;                  // 4096 = 32*128
        wsT[idx & 127][idx >> 7] = wr[idx];
    }

    // prefetch chunk 0: 1024 elems, 4/thread
    float pf[4];
#pragma unroll
    for (int l = 0; l < 4; l++) {
        int idx = tid + l * 256;
        pf[l] = xb[(size_t)(idx >> 5) * HW + (idx & 31)];
    }
#pragma unroll
    for (int l = 0; l < 4; l++) {
        int idx = tid + l * 256;
        xs[0][idx >> 5][idx & 31] = pf[l];
    }
    __syncthreads();

    u64 acc[2] = {0, 0};

#pragma unroll
    for (int kc = 0; kc < 4; kc++) {
        const int cur = kc & 1;
        if (kc < 3) {
#pragma unroll
            for (int l = 0; l < 4; l++) {
                int idx = tid + l * 256;
                pf[l] = xb[(size_t)((kc + 1) * 32 + (idx >> 5)) * HW + (idx & 31)];
            }
        }

        float breg[32];
#pragma unroll
        for (int k = 0; k < 32; k++) breg[k] = wsT[kc * 32 + k][lane];

#pragma unroll
        for (int k = 0; k < 32; k++) {
            const float4 v = *(const float4*)&xs[cur][k][pxw];   // uniform bcast 16B
            const u64 b2 = pack2(breg[k], breg[k]);
            ffma2(acc[0], pack2(v.x, v.y), b2);
            ffma2(acc[1], pack2(v.z, v.w), b2);
        }

        if (kc < 3) {
#pragma unroll
            for (int l = 0; l < 4; l++) {
                int idx = tid + l * 256;
                xs[1 - cur][idx >> 5][idx & 31] = pf[l];
            }
            __syncthreads();
        }
    }

    const float bias = br[lane];
#pragma unroll
    for (int p = 0; p < 2; p++) {
        float f0, f1; unpack2(acc[p], f0, f1);
        g_red[(px0 + pxw + 2 * p + 0) * 32 + lane] = f0 + bias;   // coalesced 128B
        g_red[(px0 + pxw + 2 * p + 1) * 32 + lane] = f1 + bias;
    }
}

// ---------------------------------------------------------------------------
// Kernel 2: ker[b][o][hw] = sum_k red[px][k] * w_span[o][k] + b_span[o]
// Rank-1 tiles: 256 px x 56 outs per block (8 warps x 7 outs, 8 px/lane).
// Grid (64, 7). f32x2 math. K=32 fully unrolled.
// ---------------------------------------------------------------------------
__global__ __launch_bounds__(256) void k_span(const float* __restrict__ wsp,
                                              const float* __restrict__ bs) {
    __shared__ float rs[CR][258];      // [k][px], EVEN pad: rows 8B-aligned
    __shared__ float ws[56 * 32];      // [o_local][k]
    const int tid  = threadIdx.x;
    const int lane = tid & 31;
    const int warp = tid >> 5;
    const int px0  = blockIdx.x * 256;
    const int o0   = blockIdx.y * 56;
    const int b    = px0 >> 12;
    const int hw0  = px0 & 4095;

    // stage red tile, transposing [px][k] -> rs[k][px]
#pragma unroll
    for (int l = 0; l < 32; l++) {
        int idx = tid + l * 256;                  // 8192 = 256*32
        int px = idx >> 5, k = idx & 31;
        rs[k][px] = g_red[(px0 + px) * 32 + k];   // 128B coalesced reads
    }
#pragma unroll
    for (int l = 0; l < 7; l++) {
        int idx = tid + l * 256;                  // 1792 = 56*32
        ws[idx] = wsp[o0 * 32 + idx];
    }
    __syncthreads();

    u64 acc[4][7] = {};

#pragma unroll
    for (int k = 0; k < 32; k++) {
        u64 a[4];
#pragma unroll
        for (int v = 0; v < 4; v++)
            a[v] = *(const u64*)&rs[k][2 * lane + 64 * v];
#pragma unroll
        for (int j = 0; j < 7; j++) {
            const float bv = ws[(warp * 7 + j) * 32 + k];   // uniform bcast
            const u64 b2 = pack2(bv, bv);
#pragma unroll
            for (int v = 0; v < 4; v++) ffma2(acc[v][j], a[v], b2);
        }
    }

#pragma unroll
    for (int j = 0; j < 7; j++) {
        const int o = o0 + warp * 7 + j;
        const float bias = bs[o];
        float* kp = g_ker + ((size_t)b * KKG + o) * HW + hw0;
#pragma unroll
        for (int v = 0; v < 4; v++) {
            float f0, f1; unpack2(acc[v][j], f0, f1);
            *(float2*)&kp[2 * lane + 64 * v] = make_float2(f0 + bias, f1 + bias);
        }
    }
}

// ---------------------------------------------------------------------------
// Kernel 3: involution. Block = 128 thr (16x8), 32x8 spatial tile, grid 512.
// Thread owns 2 horizontal px: 1 LDS.64 + 1 FFMA2 per tap serves both.
// 49 f32x2 dynamic-kernel values in regs, reused over 16 channels.
// 128 thr/CTA -> ~18K regs/CTA -> 3 CTAs/SM despite 98-reg kreg.
// ---------------------------------------------------------------------------
__global__ __launch_bounds__(128) void k_inv(const float* __restrict__ x,
                                             float* __restrict__ out) {
    __shared__ float xs[4][20][48];    // 4 channels, 20x44 patch (stride 48)
    const int tx = threadIdx.x, ty = threadIdx.y;   // (16,8)
    const int tid = ty * 16 + tx;
    const int tx0 = blockIdx.x * 32, ty0 = blockIdx.y * 8;
    const int bg = blockIdx.z;
    const int b = bg >> 3, g = bg & 7;
    const int pix = (ty0 + ty) * 64 + tx0 + 2 * tx;   // even -> 8B aligned

    // 49 per-pixel kernel pairs -> registers (coalesced LDG.64)
    const float* kb = g_ker + ((size_t)b * KKG + g * KK) * HW + pix;
    u64 kreg[49];
#pragma unroll
    for (int kk = 0; kk < 49; kk++) kreg[kk] = *(const u64*)&kb[(size_t)kk * HW];

    const float* xb = x + ((size_t)b * C + g * CG) * HW;
    float* ob = out + ((size_t)b * C + g * CG) * HW + pix;

    for (int c0 = 0; c0 < CG; c0 += 4) {
        __syncthreads();
        // stage 4 channels: 20 rows x 44 cols each (880 elems, 128 thr)
#pragma unroll
        for (int cc = 0; cc < 4; cc++) {
            const float* xc = xb + (size_t)(c0 + cc) * HW;
#pragma unroll
            for (int l = 0; l < 7; l++) {
                int idx = tid + l * 128;
                if (idx < 20 * 44) {
                    int r    = idx / 44;
                    int ccol = idx - r * 44;
                    int gy = ty0 - 6 + r;
                    int gx = tx0 - 6 + ccol;
                    float v = 0.f;
                    if (gy >= 0 && gy < 64 && gx >= 0 && gx < 64)
                        v = xc[gy * 64 + gx];
                    xs[cc][r][ccol] = v;
                }
            }
        }
        __syncthreads();

#pragma unroll
        for (int cc = 0; cc < 4; cc++) {
            u64 acc = 0;
#pragma unroll
            for (int i = 0; i < 7; i++)
#pragma unroll
                for (int j = 0; j < 7; j++) {
                    const u64 v = *(const u64*)&xs[cc][ty + 2 * i][2 * tx + 2 * j];
                    ffma2(acc, v, kreg[i * 7 + j]);
                }
            float f0, f1; unpack2(acc, f0, f1);
            *(float2*)&ob[(size_t)(c0 + cc) * HW] = make_float2(f0, f1);
        }
    }
}

// ---------------------------------------------------------------------------
extern "C" void kernel_launch(void* const* d_in, const int* in_sizes, int n_in,
                              void* d_out, int out_size) {
    const float* x   = (const float*)d_in[0];   // [4,128,64,64]
    const float* wr  = (const float*)d_in[1];   // [32,128]
    const float* br  = (const float*)d_in[2];   // [32]
    const float* wsp = (const float*)d_in[3];   // [392,32]
    const float* bsp = (const float*)d_in[4];   // [392]
    float* out = (float*)d_out;

    k_reduce<<<512, 256>>>(x, wr, br);
    k_span<<<dim3(64, 7), 256>>>(wsp, bsp);
    k_inv<<<dim3(2, 8, 32), dim3(16, 8)>>>(x, out);
}

// round 8
// speedup vs baseline: 1.0040x; 1.0040x over previous
#include <cuda_runtime.h>

#define HW   4096
#define C    128
#define CR   32
#define G    8
#define CG   16
#define KK   49
#define KKG  392
#define NPX  16384   // B * H * W

typedef unsigned long long u64;

// ---- packed f32x2 helpers (sm_103a) ---------------------------------------
__device__ __forceinline__ u64 pack2(float x, float y) {
    u64 r; asm("mov.b64 %0, {%1, %2};" : "=l"(r) : "f"(x), "f"(y)); return r;
}
__device__ __forceinline__ void unpack2(u64 v, float& x, float& y) {
    asm("mov.b64 {%0, %1}, %2;" : "=f"(x), "=f"(y) : "l"(v));
}
__device__ __forceinline__ void ffma2(u64& d, u64 a, u64 b) {
    asm("fma.rn.f32x2 %0, %1, %2, %0;" : "+l"(d) : "l"(a), "l"(b));
}

// Scratch (16B-aligned: we do float2/u64 accesses into these)
__device__ __align__(16) float g_red[NPX * CR];        // [px][32]
__device__ __align__(16) float g_ker[4 * KKG * HW];    // [b][392][hw]

// ---------------------------------------------------------------------------
// Kernel 1: red[px][o] = sum_c x[b,c,hw] * w_reduce[o,c] + b_reduce[o]
// lane = out (32 outs = warp), warp owns 4 px. Tile 32 px -> grid 512.
// Double-buffered x chunks. launch_bounds(256,2): regs<=128 so breg[32]
// stays resident and ptxas can software-pipeline (R5 had regs=32 -> spills).
// ---------------------------------------------------------------------------
__global__ __launch_bounds__(256, 2) void k_reduce(const float* __restrict__ x,
                                                   const float* __restrict__ wr,
                                                   const float* __restrict__ br) {
    __shared__ float wsT[C][CR + 2];    // [c][o], even pad -> 8B rows
    __shared__ float xs[2][32][32];     // ping-pong [k][px]
    const int tid  = threadIdx.x;
    const int lane = tid & 31;          // = out channel
    const int warp = tid >> 5;
    const int pxw  = warp * 4;          // warp's px base (4 px/warp)
    const int px0  = blockIdx.x * 32;
    const int b    = px0 >> 12;
    const int hw0  = px0 & 4095;
    const float* xb = x + (size_t)b * C * HW + hw0;

    // stage w_reduce transposed once: wsT[c][o]
#pragma unroll
    for (int l = 0; l < 16; l++) {
        int idx = tid + l * 256;                  // 4096 = 32*128
        wsT[idx & 127][idx >> 7] = wr[idx];
    }

    // prefetch chunk 0: 1024 elems, 4/thread
    float pf[4];
#pragma unroll
    for (int l = 0; l < 4; l++) {
        int idx = tid + l * 256;
        pf[l] = xb[(size_t)(idx >> 5) * HW + (idx & 31)];
    }
#pragma unroll
    for (int l = 0; l < 4; l++) {
        int idx = tid + l * 256;
        xs[0][idx >> 5][idx & 31] = pf[l];
    }
    __syncthreads();

    u64 acc[2] = {0, 0};

#pragma unroll
    for (int kc = 0; kc < 4; kc++) {
        const int cur = kc & 1;
        if (kc < 3) {
#pragma unroll
            for (int l = 0; l < 4; l++) {
                int idx = tid + l * 256;
                pf[l] = xb[(size_t)((kc + 1) * 32 + (idx >> 5)) * HW + (idx & 31)];
            }
        }

        float breg[32];
#pragma unroll
        for (int k = 0; k < 32; k++) breg[k] = wsT[kc * 32 + k][lane];

#pragma unroll
        for (int k = 0; k < 32; k++) {
            const float4 v = *(const float4*)&xs[cur][k][pxw];   // uniform bcast 16B
            const u64 b2 = pack2(breg[k], breg[k]);
            ffma2(acc[0], pack2(v.x, v.y), b2);
            ffma2(acc[1], pack2(v.z, v.w), b2);
        }

        if (kc < 3) {
#pragma unroll
            for (int l = 0; l < 4; l++) {
                int idx = tid + l * 256;
                xs[1 - cur][idx >> 5][idx & 31] = pf[l];
            }
            __syncthreads();
        }
    }

    const float bias = br[lane];
#pragma unroll
    for (int p = 0; p < 2; p++) {
        float f0, f1; unpack2(acc[p], f0, f1);
        g_red[(px0 + pxw + 2 * p + 0) * 32 + lane] = f0 + bias;   // coalesced 128B
        g_red[(px0 + pxw + 2 * p + 1) * 32 + lane] = f1 + bias;
    }
}

// ---------------------------------------------------------------------------
// Kernel 2: ker[b][o][hw] = sum_k red[px][k] * w_span[o][k] + b_span[o]
// 128 px x 56 outs per block (8 warps x 7 outs, 4 px/lane -> acc[2][7]=28 regs).
// Grid (128, 7) = 896 blocks, 3 CTAs/SM. K=32 fully unrolled, f32x2 math.
// ---------------------------------------------------------------------------
__global__ __launch_bounds__(256, 3) void k_span(const float* __restrict__ wsp,
                                                 const float* __restrict__ bs) {
    __shared__ float rs[CR][130];      // [k][px], EVEN pad: rows 8B-aligned
    __shared__ float ws[56 * 32];      // [o_local][k]
    const int tid  = threadIdx.x;
    const int lane = tid & 31;
    const int warp = tid >> 5;
    const int px0  = blockIdx.x * 128;
    const int o0   = blockIdx.y * 56;
    const int b    = px0 >> 12;
    const int hw0  = px0 & 4095;

    // stage red tile, transposing [px][k] -> rs[k][px]  (4096 elems)
#pragma unroll
    for (int l = 0; l < 16; l++) {
        int idx = tid + l * 256;
        int px = idx >> 5, k = idx & 31;
        rs[k][px] = g_red[(px0 + px) * 32 + k];   // 128B coalesced reads
    }
#pragma unroll
    for (int l = 0; l < 7; l++) {
        int idx = tid + l * 256;                  // 1792 = 56*32
        ws[idx] = wsp[o0 * 32 + idx];
    }
    __syncthreads();

    u64 acc[2][7] = {};

#pragma unroll
    for (int k = 0; k < 32; k++) {
        const u64 a0 = *(const u64*)&rs[k][2 * lane];
        const u64 a1 = *(const u64*)&rs[k][2 * lane + 64];
#pragma unroll
        for (int j = 0; j < 7; j++) {
            const float bv = ws[(warp * 7 + j) * 32 + k];   // uniform bcast
            const u64 b2 = pack2(bv, bv);
            ffma2(acc[0][j], a0, b2);
            ffma2(acc[1][j], a1, b2);
        }
    }

#pragma unroll
    for (int j = 0; j < 7; j++) {
        const int o = o0 + warp * 7 + j;
        const float bias = bs[o];
        float* kp = g_ker + ((size_t)b * KKG + o) * HW + hw0;
#pragma unroll
        for (int v = 0; v < 2; v++) {
            float f0, f1; unpack2(acc[v][j], f0, f1);
            *(float2*)&kp[2 * lane + 64 * v] = make_float2(f0 + bias, f1 + bias);
        }
    }
}

// ---------------------------------------------------------------------------
// Kernel 3: involution (R4 config: best measured). Block 256 thr (16x16),
// 32x16 spatial tile, grid (2,4,32)=256. Thread owns 2 horizontal px:
// 1 LDS.64 + 1 FFMA2 per tap serves both. 49 f32x2 kernel values in regs,
// reused over 16 channels. launch_bounds(256,1): kreg must not spill.
// ---------------------------------------------------------------------------
__global__ __launch_bounds__(256, 1) void k_inv(const float* __restrict__ x,
                                                float* __restrict__ out) {
    __shared__ float xs[4][28][48];    // 4 channels, 28x44 patch (stride 48)
    const int tx = threadIdx.x, ty = threadIdx.y;   // (16,16)
    const int tid = ty * 16 + tx;
    const int tx0 = blockIdx.x * 32, ty0 = blockIdx.y * 16;
    const int bg = blockIdx.z;
    const int b = bg >> 3, g = bg & 7;
    const int pix = (ty0 + ty) * 64 + tx0 + 2 * tx;   // even -> 8B aligned

    // 49 per-pixel kernel pairs -> registers (coalesced LDG.64)
    const float* kb = g_ker + ((size_t)b * KKG + g * KK) * HW + pix;
    u64 kreg[49];
#pragma unroll
    for (int kk = 0; kk < 49; kk++) kreg[kk] = *(const u64*)&kb[(size_t)kk * HW];

    const float* xb = x + ((size_t)b * C + g * CG) * HW;
    float* ob = out + ((size_t)b * C + g * CG) * HW + pix;

    for (int c0 = 0; c0 < CG; c0 += 4) {
        __syncthreads();
        // stage 4 channels: 28 rows x 44 cols each
#pragma unroll
        for (int cc = 0; cc < 4; cc++) {
            const float* xc = xb + (size_t)(c0 + cc) * HW;
#pragma unroll
            for (int l = 0; l < 5; l++) {
                int idx = tid + l * 256;
                if (idx < 28 * 44) {
                    int r    = idx / 44;
                    int ccol = idx - r * 44;
                    int gy = ty0 - 6 + r;
                    int gx = tx0 - 6 + ccol;
                    float v = 0.f;
                    if (gy >= 0 && gy < 64 && gx >= 0 && gx < 64)
                        v = xc[gy * 64 + gx];
                    xs[cc][r][ccol] = v;
                }
            }
        }
        __syncthreads();

#pragma unroll
        for (int cc = 0; cc < 4; cc++) {
            u64 acc = 0;
#pragma unroll
            for (int i = 0; i < 7; i++)
#pragma unroll
                for (int j = 0; j < 7; j++) {
                    const u64 v = *(const u64*)&xs[cc][ty + 2 * i][2 * tx + 2 * j];
                    ffma2(acc, v, kreg[i * 7 + j]);
                }
            float f0, f1; unpack2(acc, f0, f1);
            *(float2*)&ob[(size_t)(c0 + cc) * HW] = make_float2(f0, f1);
        }
    }
}

// ---------------------------------------------------------------------------
extern "C" void kernel_launch(void* const* d_in, const int* in_sizes, int n_in,
                              void* d_out, int out_size) {
    const float* x   = (const float*)d_in[0];   // [4,128,64,64]
    const float* wr  = (const float*)d_in[1];   // [32,128]
    const float* br  = (const float*)d_in[2];   // [32]
    const float* wsp = (const float*)d_in[3];   // [392,32]
    const float* bsp = (const float*)d_in[4];   // [392]
    float* out = (float*)d_out;

    k_reduce<<<512, 256>>>(x, wr, br);
    k_span<<<dim3(128, 7), 256>>>(wsp, bsp);
    k_inv<<<dim3(2, 4, 32), dim3(16, 16)>>>(x, out);
}